// round 1
// baseline (speedup 1.0000x reference)
#include <cuda_runtime.h>
#include <math.h>

// Problem constants
#define Bv 8
#define Lv 2048
#define Dv 64
#define BM 16          // query rows per CTA
#define BK 128         // k-tile
#define NT 256         // threads per CTA
#define SCALE 0.125f   // 1/sqrt(64)

// SMEM layout (floats):
//   S   : BM*Lv           = 32768   full score/prob row-block
//   Qt  : BM*Dv           = 1024
//   Ct  : Dv*(BK+1)       = 8256    (phase1: transposed+padded; phase2: [BK][Dv] fits)
//   red : NT              = 256
//   rmax: BM, rinv: BM    = 32
#define SMEM_FLOATS (BM*Lv + BM*Dv + Dv*(BK+1) + NT + 2*BM)

__global__ __launch_bounds__(NT, 1)
void attn_fused_kernel(const float* __restrict__ Q,
                       const float* __restrict__ C,
                       const unsigned char* __restrict__ M,
                       float* __restrict__ out,
                       float* __restrict__ att)
{
    extern __shared__ float sm[];
    float* S    = sm;                    // BM*Lv
    float* Qt   = S + BM*Lv;             // BM*Dv
    float* Ct   = Qt + BM*Dv;            // Dv*(BK+1)
    float* red  = Ct + Dv*(BK+1);        // NT
    float* rmax = red + NT;              // BM
    float* rinv = rmax + BM;             // BM

    const int t  = threadIdx.x;
    const int b  = blockIdx.y;
    const int q0 = blockIdx.x * BM;

    const float* Qg = Q + (size_t)(b*Lv + q0) * Dv;
    const float* Cg = C + (size_t)b * Lv * Dv;
    const unsigned char* Mg = M + (size_t)(b*Lv + q0) * Lv;

    // Load Q tile (coalesced)
    for (int i = t; i < BM*Dv; i += NT) Qt[i] = Qg[i];

    const int ty = t >> 6;   // 0..3  -> owns rows 4*ty .. 4*ty+3
    const int tx = t & 63;   // 0..63 -> owns cols tx, tx+64 (phase1) / col tx (phase2)

    // ============ Phase 1: S = Q @ C^T * scale (masked) ============
    for (int kt = 0; kt < Lv/BK; ++kt) {
        __syncthreads();   // previous iteration's Ct reads done (and Qt visible on iter 0)
        // Load C k-tile TRANSPOSED with pad: Ct[d*(BK+1)+k] = C[k0+k][d]
        for (int i = t; i < BK*Dv; i += NT) {
            int k = i >> 6, d = i & 63;
            Ct[d*(BK+1) + k] = Cg[(size_t)(kt*BK)*Dv + i];
        }
        __syncthreads();

        float acc[4][2] = {};
        #pragma unroll
        for (int d = 0; d < Dv; ++d) {
            float c0 = Ct[d*(BK+1) + tx];        // conflict-free (consecutive lanes)
            float c1 = Ct[d*(BK+1) + tx + 64];
            #pragma unroll
            for (int j = 0; j < 4; ++j) {
                float q = Qt[(ty*4 + j)*Dv + d]; // warp-broadcast
                acc[j][0] = fmaf(q, c0, acc[j][0]);
                acc[j][1] = fmaf(q, c1, acc[j][1]);
            }
        }
        #pragma unroll
        for (int j = 0; j < 4; ++j) {
            const int r = ty*4 + j;
            #pragma unroll
            for (int c = 0; c < 2; ++c) {
                const int k = kt*BK + tx + c*64;
                float v = acc[j][c] * SCALE;
                if (Mg[(size_t)r*Lv + k]) v = -INFINITY;
                S[r*Lv + k] = v;
            }
        }
    }
    __syncthreads();

    // ============ Softmax over each of the BM rows (len Lv) ============
    const int sub = t & 15;   // 16 threads per row
    const int row = t >> 4;   // 0..15

    float lmax = -INFINITY;
    for (int k = sub; k < Lv; k += 16)
        lmax = fmaxf(lmax, S[row*Lv + k]);
    red[t] = lmax;
    __syncthreads();
    if (t < BM) {
        float m = -INFINITY;
        #pragma unroll
        for (int i = 0; i < 16; ++i) m = fmaxf(m, red[t*16 + i]);
        rmax[t] = m;
    }
    __syncthreads();

    const float m = rmax[row];
    float lsum = 0.f;
    for (int k = sub; k < Lv; k += 16) {
        float e = __expf(S[row*Lv + k] - m);
        S[row*Lv + k] = e;
        lsum += e;
    }
    red[t] = lsum;
    __syncthreads();
    if (t < BM) {
        float s = 0.f;
        #pragma unroll
        for (int i = 0; i < 16; ++i) s += red[t*16 + i];
        rinv[t] = 1.0f / s;
    }
    __syncthreads();

    // ============ Normalize in SMEM + stream att to GMEM ============
    float* attb = att + (size_t)(b*Lv + q0) * Lv;
    for (int i = 0; i < BM; ++i) {
        const float inv = rinv[i];
        for (int k = t; k < Lv; k += NT) {
            float v = S[i*Lv + k] * inv;
            S[i*Lv + k] = v;
            attb[(size_t)i*Lv + k] = v;   // coalesced
        }
    }

    // ============ Phase 2: out = P @ C ============
    float acc2[4] = {0.f, 0.f, 0.f, 0.f};
    for (int kt = 0; kt < Lv/BK; ++kt) {
        __syncthreads();   // also covers normalize-pass completion on iter 0
        // Load C k-tile row-major: Ct[k*Dv + d]
        for (int i = t; i < BK*Dv; i += NT)
            Ct[i] = Cg[(size_t)(kt*BK)*Dv + i];
        __syncthreads();

        #pragma unroll 8
        for (int k = 0; k < BK; ++k) {
            float c = Ct[k*Dv + tx];             // conflict-free
            #pragma unroll
            for (int j = 0; j < 4; ++j)
                acc2[j] = fmaf(S[(ty*4 + j)*Lv + kt*BK + k], c, acc2[j]); // broadcast
        }
    }

    float* outb = out + (size_t)(b*Lv + q0) * Dv;
    #pragma unroll
    for (int j = 0; j < 4; ++j)
        outb[(size_t)(ty*4 + j)*Dv + tx] = acc2[j];   // coalesced
}

extern "C" void kernel_launch(void* const* d_in, const int* in_sizes, int n_in,
                              void* d_out, int out_size) {
    const float* Q = (const float*)d_in[0];
    const float* C = (const float*)d_in[1];
    const unsigned char* M = (const unsigned char*)d_in[2];

    float* out = (float*)d_out;                       // [B, L, D]
    float* att = out + (size_t)Bv * Lv * Dv;          // [B, L, L] follows

    const size_t smem_bytes = (size_t)SMEM_FLOATS * sizeof(float);  // ~165.4 KB
    cudaFuncSetAttribute(attn_fused_kernel,
                         cudaFuncAttributeMaxDynamicSharedMemorySize,
                         (int)smem_bytes);

    dim3 grid(Lv / BM, Bv);
    attn_fused_kernel<<<grid, NT, smem_bytes>>>(Q, C, M, out, att);
}

// round 2
// speedup vs baseline: 1.1604x; 1.1604x over previous
#include <cuda_runtime.h>
#include <math.h>

#define Bv 8
#define Lv 2048
#define Dv 64
#define BM 16          // query rows per CTA (= #warps)
#define BK 128         // k-tile
#define NT 512         // 16 warps
#define SCALE 0.125f   // 1/sqrt(64)
#define SROW 2052      // padded S row stride (floats), multiple of 4
#define CT1S 132       // phase-1 transposed C-tile row stride (floats), multiple of 4
#define CTBUF (Dv*CT1S)  // one C-tile buffer: 8448 floats (phase2 uses 8192 of it)

// smem floats: S 16*2052 + Qt 1024 + Ct 2*8448  = 50752 floats = 203,008 B
#define SMEM_FLOATS (BM*SROW + BM*Dv + 2*CTBUF)

__global__ __launch_bounds__(NT, 1)
void attn_fused_kernel(const float* __restrict__ Q,
                       const float* __restrict__ C,
                       const unsigned char* __restrict__ M,
                       float* __restrict__ out,
                       float* __restrict__ att)
{
    extern __shared__ float sm[];
    float* S  = sm;                  // [BM][SROW]
    float* Qt = S + BM*SROW;         // [BM][Dv]
    float* Ct = Qt + BM*Dv;          // 2 buffers

    const int t    = threadIdx.x;
    const int lane = t & 31;
    const int w    = t >> 5;         // warp id == row within CTA tile (0..15)
    const int b    = blockIdx.y;
    const int q0   = blockIdx.x * BM;

    const float* Qg = Q + (size_t)(b*Lv + q0) * Dv;
    const float* Cg = C + (size_t)b * Lv * Dv;
    const unsigned char* Mg = M + (size_t)(b*Lv + q0) * Lv;

    // ---- load Q tile (coalesced float4) ----
    if (t < BM*Dv/4) ((float4*)Qt)[t] = ((const float4*)Qg)[t];

    // ---- preload phase-1 tile 0, transposed: Ct[d][k] = Ctile[k][d] ----
    const int d_tr  = t & 63;        // column (d) this thread writes
    const int k0_tr = t >> 6;        // base k, +8j
    float r[16];
    #pragma unroll
    for (int j = 0; j < 16; ++j) r[j] = Cg[t + 512*j];
    #pragma unroll
    for (int j = 0; j < 16; ++j) Ct[d_tr*CT1S + k0_tr + 8*j] = r[j];
    __syncthreads();

    // ================= Phase 1: S = Q @ C^T * scale (masked) =================
    // thread: row = w, cols = 4*lane .. 4*lane+3 within each k-tile
    const float4* Qt4 = (const float4*)(Qt + w*Dv);   // 16 float4, uniform per warp
    #pragma unroll 1
    for (int kt = 0; kt < Lv/BK; ++kt) {
        const float* buf = Ct + (kt & 1) * CTBUF;
        if (kt < Lv/BK - 1) {
            const float* src = Cg + (size_t)(kt+1)*BK*Dv;
            #pragma unroll
            for (int j = 0; j < 16; ++j) r[j] = src[t + 512*j];
        }

        float4 acc = {0.f, 0.f, 0.f, 0.f};
        const float4* B4 = (const float4*)buf;        // row stride 33 float4
        #pragma unroll
        for (int dd = 0; dd < 16; ++dd) {
            const float4 q4 = Qt4[dd];                 // broadcast LDS.128
            float4 c;
            c = B4[(4*dd+0)*33 + lane];
            acc.x = fmaf(q4.x, c.x, acc.x); acc.y = fmaf(q4.x, c.y, acc.y);
            acc.z = fmaf(q4.x, c.z, acc.z); acc.w = fmaf(q4.x, c.w, acc.w);
            c = B4[(4*dd+1)*33 + lane];
            acc.x = fmaf(q4.y, c.x, acc.x); acc.y = fmaf(q4.y, c.y, acc.y);
            acc.z = fmaf(q4.y, c.z, acc.z); acc.w = fmaf(q4.y, c.w, acc.w);
            c = B4[(4*dd+2)*33 + lane];
            acc.x = fmaf(q4.z, c.x, acc.x); acc.y = fmaf(q4.z, c.y, acc.y);
            acc.z = fmaf(q4.z, c.z, acc.z); acc.w = fmaf(q4.z, c.w, acc.w);
            c = B4[(4*dd+3)*33 + lane];
            acc.x = fmaf(q4.w, c.x, acc.x); acc.y = fmaf(q4.w, c.y, acc.y);
            acc.z = fmaf(q4.w, c.z, acc.z); acc.w = fmaf(q4.w, c.w, acc.w);
        }

        if (kt < Lv/BK - 1) {
            float* nbuf = Ct + ((kt+1) & 1) * CTBUF;
            #pragma unroll
            for (int j = 0; j < 16; ++j) nbuf[d_tr*CT1S + k0_tr + 8*j] = r[j];
        }

        // mask + store scores to S (warp-local row)
        const uchar4 mk = ((const uchar4*)(Mg + (size_t)w*Lv + kt*BK))[lane];
        float4 v;
        v.x = acc.x * SCALE; v.y = acc.y * SCALE;
        v.z = acc.z * SCALE; v.w = acc.w * SCALE;
        if (mk.x) v.x = -INFINITY;
        if (mk.y) v.y = -INFINITY;
        if (mk.z) v.z = -INFINITY;
        if (mk.w) v.w = -INFINITY;
        ((float4*)(S + w*SROW + kt*BK))[lane] = v;
        __syncthreads();   // Ct buffer handoff
    }

    // ================= Softmax: warp w owns row w, pure shuffles =============
    float4* Sr = (float4*)(S + w*SROW);   // 512 float4 per row
    float mx = -INFINITY;
    #pragma unroll
    for (int i = 0; i < 16; ++i) {
        float4 v = Sr[lane + 32*i];
        mx = fmaxf(mx, fmaxf(fmaxf(v.x, v.y), fmaxf(v.z, v.w)));
    }
    #pragma unroll
    for (int o = 16; o; o >>= 1) mx = fmaxf(mx, __shfl_xor_sync(0xffffffffu, mx, o));

    float sum = 0.f;
    #pragma unroll
    for (int i = 0; i < 16; ++i) {
        float4 v = Sr[lane + 32*i];
        v.x = __expf(v.x - mx); v.y = __expf(v.y - mx);
        v.z = __expf(v.z - mx); v.w = __expf(v.w - mx);
        Sr[lane + 32*i] = v;                 // S holds unnormalized e
        sum += (v.x + v.y) + (v.z + v.w);
    }
    #pragma unroll
    for (int o = 16; o; o >>= 1) sum += __shfl_xor_sync(0xffffffffu, sum, o);
    const float inv = 1.0f / sum;
    __syncwarp();

    // ---- prefetch phase-2 tile 0 (natural layout) while writing att ----
    float4 p4[4];
    #pragma unroll
    for (int j = 0; j < 4; ++j) p4[j] = ((const float4*)Cg)[t + 512*j];

    float4* attr = (float4*)(att + (size_t)(b*Lv + q0 + w) * Lv);
    #pragma unroll
    for (int i = 0; i < 16; ++i) {
        float4 v = Sr[lane + 32*i];
        v.x *= inv; v.y *= inv; v.z *= inv; v.w *= inv;
        attr[lane + 32*i] = v;               // coalesced normalized att
    }

    // phase-1 Ct reads all ended at the kt=15 barrier; safe to overwrite now
    #pragma unroll
    for (int j = 0; j < 4; ++j) ((float4*)Ct)[t + 512*j] = p4[j];
    __syncthreads();

    // ================= Phase 2: out = (e @ C) * inv ==========================
    // thread: row = w, cols = 2*lane, 2*lane+1
    float2 acc2 = {0.f, 0.f};
    const float* Srow = S + w*SROW;
    #pragma unroll 1
    for (int kt = 0; kt < Lv/BK; ++kt) {
        const float* buf = Ct + (kt & 1) * CTBUF;
        if (kt < Lv/BK - 1) {
            const float4* src = (const float4*)(Cg + (size_t)(kt+1)*BK*Dv);
            #pragma unroll
            for (int j = 0; j < 4; ++j) p4[j] = src[t + 512*j];
        }

        const float2* B2 = (const float2*)buf;             // [128][32] float2
        const float4* S4r = (const float4*)(Srow + kt*BK); // uniform per warp
        #pragma unroll 8
        for (int kk = 0; kk < 32; ++kk) {
            const float4 s4 = S4r[kk];                     // broadcast LDS.128
            float2 c;
            c = B2[(4*kk+0)*32 + lane];
            acc2.x = fmaf(s4.x, c.x, acc2.x); acc2.y = fmaf(s4.x, c.y, acc2.y);
            c = B2[(4*kk+1)*32 + lane];
            acc2.x = fmaf(s4.y, c.x, acc2.x); acc2.y = fmaf(s4.y, c.y, acc2.y);
            c = B2[(4*kk+2)*32 + lane];
            acc2.x = fmaf(s4.z, c.x, acc2.x); acc2.y = fmaf(s4.z, c.y, acc2.y);
            c = B2[(4*kk+3)*32 + lane];
            acc2.x = fmaf(s4.w, c.x, acc2.x); acc2.y = fmaf(s4.w, c.y, acc2.y);
        }

        if (kt < Lv/BK - 1) {
            float4* nbuf = (float4*)(Ct + ((kt+1) & 1) * CTBUF);
            #pragma unroll
            for (int j = 0; j < 4; ++j) nbuf[t + 512*j] = p4[j];
        }
        __syncthreads();
    }

    float2 o2;
    o2.x = acc2.x * inv;
    o2.y = acc2.y * inv;
    ((float2*)(out + (size_t)(b*Lv + q0 + w) * Dv))[lane] = o2;
}

extern "C" void kernel_launch(void* const* d_in, const int* in_sizes, int n_in,
                              void* d_out, int out_size) {
    const float* Q = (const float*)d_in[0];
    const float* C = (const float*)d_in[1];
    const unsigned char* M = (const unsigned char*)d_in[2];

    float* out = (float*)d_out;                   // [B, L, D]
    float* att = out + (size_t)Bv * Lv * Dv;      // [B, L, L]

    const size_t smem_bytes = (size_t)SMEM_FLOATS * sizeof(float);  // ~203 KB
    cudaFuncSetAttribute(attn_fused_kernel,
                         cudaFuncAttributeMaxDynamicSharedMemorySize,
                         (int)smem_bytes);

    dim3 grid(Lv / BM, Bv);
    attn_fused_kernel<<<grid, NT, smem_bytes>>>(Q, C, M, out, att);
}